// round 7
// baseline (speedup 1.0000x reference)
#include <cuda_runtime.h>
#include <cuda_bf16.h>
#include <cstdint>

#define B_ 16
#define Q_ 2048
#define S_ 2048
#define D_ 128
#define SHIFT 12.0f
#define NSB (S_ / 128)   // 16 s-blocks per row

// byte-level swizzle for 64B rows (R4-verified)
#define SWZ(o) ((o) ^ (((o) >> 3) & 0x70))

__device__ int   g_mask_mode;                // 0 = uint8, 1 = int32, 2 = float32
__device__ float g_Zp[(size_t)B_ * Q_ * NSB];// per-(row, s-block) partial sums

// ---------------------------------------------------------------------------
__global__ void k_probe_mask(const unsigned int* __restrict__ m)
{
    const int lane = threadIdx.x;
    bool i32 = true, f32 = true;
    for (int i = lane; i < 1024; i += 32) {
        unsigned int w = m[i];
        if (w > 1u) i32 = false;
        if (w != 0u && w != 0x3F800000u) f32 = false;
    }
    unsigned bi = __ballot_sync(0xffffffffu, i32);
    unsigned bf = __ballot_sync(0xffffffffu, f32);
    if (lane == 0) g_mask_mode = (bi == 0xffffffffu) ? 1 : ((bf == 0xffffffffu) ? 2 : 0);
}

// ---------------------------------------------------------------------------
__device__ __forceinline__ void split_pack(float x, float y, uint32_t& hi, uint32_t& lo)
{
    __nv_bfloat16 hx = __float2bfloat16_rn(x);
    __nv_bfloat16 hy = __float2bfloat16_rn(y);
    __nv_bfloat16 lx = __float2bfloat16_rn(x - __bfloat162float(hx));
    __nv_bfloat16 ly = __float2bfloat16_rn(y - __bfloat162float(hy));
    hi = (uint32_t)__bfloat16_as_ushort(hx) | ((uint32_t)__bfloat16_as_ushort(hy) << 16);
    lo = (uint32_t)__bfloat16_as_ushort(lx) | ((uint32_t)__bfloat16_as_ushort(ly) << 16);
}

__device__ __forceinline__ void split8(const float4& a, const float4& b, uint4& hi, uint4& lo)
{
    split_pack(a.x, a.y, hi.x, lo.x);
    split_pack(a.z, a.w, hi.y, lo.y);
    split_pack(b.x, b.y, hi.z, lo.z);
    split_pack(b.z, b.w, hi.w, lo.w);
}

__device__ __forceinline__ void mma16816(float (&c)[4], const uint32_t (&a)[4], const uint32_t* b)
{
    asm volatile(
        "mma.sync.aligned.m16n8k16.row.col.f32.bf16.bf16.f32 "
        "{%0,%1,%2,%3}, {%4,%5,%6,%7}, {%8,%9}, {%0,%1,%2,%3};\n"
        : "+f"(c[0]), "+f"(c[1]), "+f"(c[2]), "+f"(c[3])
        : "r"(a[0]), "r"(a[1]), "r"(a[2]), "r"(a[3]), "r"(b[0]), "r"(b[1]));
}

__device__ __forceinline__ void ldsm_x4(uint32_t (&r)[4], uint32_t addr)
{
    asm volatile("ldmatrix.sync.aligned.m8n8.x4.shared.b16 {%0,%1,%2,%3}, [%4];\n"
                 : "=r"(r[0]), "=r"(r[1]), "=r"(r[2]), "=r"(r[3]) : "r"(addr));
}

__device__ __forceinline__ uint32_t sptr(const void* p)
{
    return (uint32_t)__cvta_generic_to_shared(p);
}

// ---------------------------------------------------------------------------
// Kernel 1: U = mask ? 0 : exp(score*scale - SHIFT); per-(row,s-block) sums
// to g_Zp via smem reduce + plain stores (NO atomics).
// CTA 128q x 128s, 512 thr (16 warps 4x4, warp tile 32x32), D chunks of 32.
// ---------------------------------------------------------------------------
__global__ __launch_bounds__(512, 1) void k_scores(
    const float* __restrict__ Qm, const float* __restrict__ Km,
    const void* __restrict__ mask, float* __restrict__ P)
{
    __shared__ __align__(128) uint8_t sm[32768];
    __shared__ float sZp[128][4];
    uint8_t* sQh = sm;
    uint8_t* sQl = sm + 8192;
    uint8_t* sKh = sm + 16384;
    uint8_t* sKl = sm + 24576;

    const int b  = blockIdx.z;
    const int q0 = blockIdx.y * 128;
    const int s0 = blockIdx.x * 128;
    const float* Qb = Qm + ((size_t)b * Q_ + q0) * D_;
    const float* Kb = Km + ((size_t)b * S_ + s0) * D_;

    const int tid  = threadIdx.x;
    const int lane = tid & 31;
    const int wid  = tid >> 5;
    const int g    = lane >> 2;
    const int tg   = lane & 3;
    const int mw   = wid >> 2;
    const int nw   = wid & 3;

    float acc[2][4][4];
#pragma unroll
    for (int i = 0; i < 2; i++)
#pragma unroll
        for (int j = 0; j < 4; j++)
#pragma unroll
            for (int k = 0; k < 4; k++) acc[i][j][k] = 0.f;

    // conversion mapping: thread -> row r (0..127), 8-float chunk c (0..3)
    const int r = tid >> 2;
    const int c = tid & 3;
    const uint32_t sts_off = SWZ((uint32_t)(r * 64 + c * 16));

    float4 q0v, q1v, k0v, k1v;
    q0v = *(const float4*)(Qb + (size_t)r * D_ + c * 8);
    q1v = *(const float4*)(Qb + (size_t)r * D_ + c * 8 + 4);
    k0v = *(const float4*)(Kb + (size_t)r * D_ + c * 8);
    k1v = *(const float4*)(Kb + (size_t)r * D_ + c * 8 + 4);

    const uint32_t a_row[2] = { (uint32_t)(mw * 32 + 0  + (lane & 15)),
                                (uint32_t)(mw * 32 + 16 + (lane & 15)) };
    const uint32_t a_chq    = (uint32_t)(lane >> 4);
    const uint32_t b_row[2] = { (uint32_t)(nw * 32 + 0  + (lane & 7) + ((lane & 16) >> 1)),
                                (uint32_t)(nw * 32 + 16 + (lane & 7) + ((lane & 16) >> 1)) };
    const uint32_t b_chq    = (uint32_t)((lane >> 3) & 1);

    for (int dc = 0; dc < D_; dc += 32) {
        {
            uint4 h, l;
            split8(q0v, q1v, h, l);
            *(uint4*)(sQh + sts_off) = h;
            *(uint4*)(sQl + sts_off) = l;
            split8(k0v, k1v, h, l);
            *(uint4*)(sKh + sts_off) = h;
            *(uint4*)(sKl + sts_off) = l;
        }
        __syncthreads();

        if (dc + 32 < D_) {
            q0v = *(const float4*)(Qb + (size_t)r * D_ + dc + 32 + c * 8);
            q1v = *(const float4*)(Qb + (size_t)r * D_ + dc + 32 + c * 8 + 4);
            k0v = *(const float4*)(Kb + (size_t)r * D_ + dc + 32 + c * 8);
            k1v = *(const float4*)(Kb + (size_t)r * D_ + dc + 32 + c * 8 + 4);
        }

#pragma unroll
        for (int ks = 0; ks < 2; ks++) {
            uint32_t ah[2][4], al[2][4];
#pragma unroll
            for (int mi = 0; mi < 2; mi++) {
                uint32_t off = SWZ(a_row[mi] * 64 + (2 * ks + a_chq) * 16);
                ldsm_x4(ah[mi], sptr(sQh) + off);
                ldsm_x4(al[mi], sptr(sQl) + off);
            }
            uint32_t bh[2][4], bl[2][4];
#pragma unroll
            for (int njp = 0; njp < 2; njp++) {
                uint32_t off = SWZ(b_row[njp] * 64 + (2 * ks + b_chq) * 16);
                ldsm_x4(bh[njp], sptr(sKh) + off);
                ldsm_x4(bl[njp], sptr(sKl) + off);
            }
#pragma unroll
            for (int mi = 0; mi < 2; mi++)
#pragma unroll
                for (int njp = 0; njp < 2; njp++)
#pragma unroll
                    for (int j = 0; j < 2; j++) {
                        float (&cacc)[4] = acc[mi][njp * 2 + j];
                        mma16816(cacc, ah[mi], &bh[njp][2 * j]);
                        mma16816(cacc, ah[mi], &bl[njp][2 * j]);
                        mma16816(cacc, al[mi], &bh[njp][2 * j]);
                    }
        }
        __syncthreads();
    }

    const float scale = 0.08838834764831845f;  // 128^-0.5
    const int mm = g_mask_mode;
#pragma unroll
    for (int mi = 0; mi < 2; mi++) {
#pragma unroll
        for (int hh = 0; hh < 2; hh++) {
            const int row = mw * 32 + mi * 16 + hh * 8 + g;
            const size_t rowoff = ((size_t)b * Q_ + q0 + row) * (size_t)S_;
            float rsum = 0.f;
#pragma unroll
            for (int nj = 0; nj < 4; nj++) {
                const int s = s0 + nw * 32 + nj * 8 + tg * 2;
                const size_t off = rowoff + s;
                const float v0 = acc[mi][nj][hh * 2 + 0] * scale;
                const float v1 = acc[mi][nj][hh * 2 + 1] * scale;
                bool m0, m1;
                if (mm == 1) {
                    int2 w = *(const int2*)((const int*)mask + off);
                    m0 = w.x != 0; m1 = w.y != 0;
                } else if (mm == 2) {
                    float2 w = *(const float2*)((const float*)mask + off);
                    m0 = w.x != 0.f; m1 = w.y != 0.f;
                } else {
                    const unsigned char* mu = (const unsigned char*)mask + off;
                    m0 = mu[0] != 0; m1 = mu[1] != 0;
                }
                float2 o;
                o.x = m0 ? 0.f : __expf(v0 - SHIFT);
                o.y = m1 ? 0.f : __expf(v1 - SHIFT);
                rsum += o.x + o.y;
                *(float2*)(P + off) = o;
            }
            rsum += __shfl_xor_sync(0xffffffffu, rsum, 1);
            rsum += __shfl_xor_sync(0xffffffffu, rsum, 2);
            if (tg == 0) sZp[row][nw] = rsum;
        }
    }
    __syncthreads();
    if (tid < 128) {
        float z = (sZp[tid][0] + sZp[tid][1]) + (sZp[tid][2] + sZp[tid][3]);
        g_Zp[((size_t)b * Q_ + q0 + tid) * NSB + blockIdx.x] = z;
    }
}

// ---------------------------------------------------------------------------
// Kernel 2: out = (U/Z) @ V; also writes normalized attention back to P.
// CTA 128q x 128d, 512 thr, S chunks of 32, double-buffered smem (64KB).
// invZ assembled from g_Zp partials in the prologue (no atomics anywhere).
// ---------------------------------------------------------------------------
__global__ __launch_bounds__(512, 1) void k_pv(
    float* __restrict__ P, const float* __restrict__ V,
    float* __restrict__ O)
{
    extern __shared__ __align__(128) uint8_t sm[];
    // buf layout: buf*32768 + {Ph:0, Pl:8192, Vh:16384, Vl:24576}

    const int b  = blockIdx.y;
    const int q0 = blockIdx.x * 128;
    float* Pb = P + ((size_t)b * Q_ + q0) * (size_t)S_;
    const float* Vb = V + (size_t)b * S_ * D_;

    const int tid  = threadIdx.x;
    const int lane = tid & 31;
    const int wid  = tid >> 5;
    const int g    = lane >> 2;
    const int tg   = lane & 3;
    const int mw   = wid >> 2;
    const int nw   = wid & 3;

    float acc[2][4][4];
#pragma unroll
    for (int i = 0; i < 2; i++)
#pragma unroll
        for (int j = 0; j < 4; j++)
#pragma unroll
            for (int k = 0; k < 4; k++) acc[i][j][k] = 0.f;

    const int pr = tid >> 2;
    const int pc = tid & 3;
    const uint32_t p_sts = SWZ((uint32_t)(pr * 64 + pc * 16));
    const int vd = tid & 127;
    const int sg = tid >> 7;
    const uint32_t v_sts = SWZ((uint32_t)(vd * 64 + sg * 16));

    // ---- invZ from partials: quad leader sums 16 floats, broadcast ----
    float invZ;
    {
        float z = 0.f;
        if ((tid & 3) == 0) {
            const float4* zp = (const float4*)(g_Zp + ((size_t)b * Q_ + q0 + pr) * NSB);
            float4 z0 = zp[0], z1 = zp[1], z2 = zp[2], z3 = zp[3];
            z = (((z0.x + z0.y) + (z0.z + z0.w)) + ((z1.x + z1.y) + (z1.z + z1.w)))
              + (((z2.x + z2.y) + (z2.z + z2.w)) + ((z3.x + z3.y) + (z3.z + z3.w)));
        }
        z = __shfl_sync(0xffffffffu, z, lane & ~3);
        invZ = 1.0f / z;
    }

    const uint32_t a_row[2] = { (uint32_t)(mw * 32 + 0  + (lane & 15)),
                                (uint32_t)(mw * 32 + 16 + (lane & 15)) };
    const uint32_t a_chq    = (uint32_t)(lane >> 4);
    const uint32_t b_row[2] = { (uint32_t)(nw * 32 + 0  + (lane & 7) + ((lane & 16) >> 1)),
                                (uint32_t)(nw * 32 + 16 + (lane & 7) + ((lane & 16) >> 1)) };
    const uint32_t b_chq    = (uint32_t)((lane >> 3) & 1);

    // ---- prologue: chunk 0 -> buf 0 ----
    {
        float4 pp0 = *(const float4*)(Pb + (size_t)pr * S_ + pc * 8);
        float4 pp1 = *(const float4*)(Pb + (size_t)pr * S_ + pc * 8 + 4);
        pp0.x *= invZ; pp0.y *= invZ; pp0.z *= invZ; pp0.w *= invZ;
        pp1.x *= invZ; pp1.y *= invZ; pp1.z *= invZ; pp1.w *= invZ;
        *(float4*)(Pb + (size_t)pr * S_ + pc * 8)     = pp0;
        *(float4*)(Pb + (size_t)pr * S_ + pc * 8 + 4) = pp1;
        uint4 h, l;
        split8(pp0, pp1, h, l);
        *(uint4*)(sm + p_sts)        = h;
        *(uint4*)(sm + 8192 + p_sts) = l;

        float4 va, vbq;
        va.x  = Vb[(size_t)(sg * 8 + 0) * D_ + vd];
        va.y  = Vb[(size_t)(sg * 8 + 1) * D_ + vd];
        va.z  = Vb[(size_t)(sg * 8 + 2) * D_ + vd];
        va.w  = Vb[(size_t)(sg * 8 + 3) * D_ + vd];
        vbq.x = Vb[(size_t)(sg * 8 + 4) * D_ + vd];
        vbq.y = Vb[(size_t)(sg * 8 + 5) * D_ + vd];
        vbq.z = Vb[(size_t)(sg * 8 + 6) * D_ + vd];
        vbq.w = Vb[(size_t)(sg * 8 + 7) * D_ + vd];
        split8(va, vbq, h, l);
        *(uint4*)(sm + 16384 + v_sts) = h;
        *(uint4*)(sm + 24576 + v_sts) = l;
    }
    __syncthreads();

    for (int sc = 0; sc < S_; sc += 32) {
        const uint32_t cur = ((sc >> 5) & 1) * 32768u;
        const uint32_t nxt = cur ^ 32768u;
        const bool more = (sc + 32 < S_);

        float4 pp0, pp1, va, vbq;
        if (more) {
            pp0 = *(const float4*)(Pb + (size_t)pr * S_ + sc + 32 + pc * 8);
            pp1 = *(const float4*)(Pb + (size_t)pr * S_ + sc + 32 + pc * 8 + 4);
            va.x  = Vb[(size_t)(sc + 32 + sg * 8 + 0) * D_ + vd];
            va.y  = Vb[(size_t)(sc + 32 + sg * 8 + 1) * D_ + vd];
            va.z  = Vb[(size_t)(sc + 32 + sg * 8 + 2) * D_ + vd];
            va.w  = Vb[(size_t)(sc + 32 + sg * 8 + 3) * D_ + vd];
            vbq.x = Vb[(size_t)(sc + 32 + sg * 8 + 4) * D_ + vd];
            vbq.y = Vb[(size_t)(sc + 32 + sg * 8 + 5) * D_ + vd];
            vbq.z = Vb[(size_t)(sc + 32 + sg * 8 + 6) * D_ + vd];
            vbq.w = Vb[(size_t)(sc + 32 + sg * 8 + 7) * D_ + vd];
        }

#pragma unroll
        for (int ks = 0; ks < 2; ks++) {
            uint32_t ah[2][4], al[2][4];
#pragma unroll
            for (int mi = 0; mi < 2; mi++) {
                uint32_t off = cur + SWZ(a_row[mi] * 64 + (2 * ks + a_chq) * 16);
                ldsm_x4(ah[mi], sptr(sm) + off);
                ldsm_x4(al[mi], sptr(sm) + 8192 + off);
            }
            uint32_t bh[2][4], bl[2][4];
#pragma unroll
            for (int njp = 0; njp < 2; njp++) {
                uint32_t off = cur + SWZ(b_row[njp] * 64 + (2 * ks + b_chq) * 16);
                ldsm_x4(bh[njp], sptr(sm) + 16384 + off);
                ldsm_x4(bl[njp], sptr(sm) + 24576 + off);
            }
#pragma unroll
            for (int mi = 0; mi < 2; mi++)
#pragma unroll
                for (int njp = 0; njp < 2; njp++)
#pragma unroll
                    for (int j = 0; j < 2; j++) {
                        float (&cacc)[4] = acc[mi][njp * 2 + j];
                        mma16816(cacc, ah[mi], &bh[njp][2 * j]);
                        mma16816(cacc, ah[mi], &bl[njp][2 * j]);
                        mma16816(cacc, al[mi], &bh[njp][2 * j]);
                    }
        }

        if (more) {
            pp0.x *= invZ; pp0.y *= invZ; pp0.z *= invZ; pp0.w *= invZ;
            pp1.x *= invZ; pp1.y *= invZ; pp1.z *= invZ; pp1.w *= invZ;
            *(float4*)(Pb + (size_t)pr * S_ + sc + 32 + pc * 8)     = pp0;
            *(float4*)(Pb + (size_t)pr * S_ + sc + 32 + pc * 8 + 4) = pp1;
            uint4 h, l;
            split8(pp0, pp1, h, l);
            *(uint4*)(sm + nxt + p_sts)        = h;
            *(uint4*)(sm + nxt + 8192 + p_sts) = l;
            split8(va, vbq, h, l);
            *(uint4*)(sm + nxt + 16384 + v_sts) = h;
            *(uint4*)(sm + nxt + 24576 + v_sts) = l;
        }
        __syncthreads();
    }

#pragma unroll
    for (int mi = 0; mi < 2; mi++) {
#pragma unroll
        for (int hh = 0; hh < 2; hh++) {
            const int q = q0 + mw * 32 + mi * 16 + hh * 8 + g;
            float* orow = O + ((size_t)b * Q_ + q) * D_;
#pragma unroll
            for (int nj = 0; nj < 4; nj++) {
                const int d = nw * 32 + nj * 8 + tg * 2;
                float2 o = { acc[mi][nj][hh * 2], acc[mi][nj][hh * 2 + 1] };
                *(float2*)(orow + d) = o;
            }
        }
    }
}

// ---------------------------------------------------------------------------
extern "C" void kernel_launch(void* const* d_in, const int* in_sizes, int n_in,
                              void* d_out, int out_size)
{
    const size_t MASK_N = (size_t)B_ * Q_ * S_;
    const void* mask = nullptr;
    const float* vkq[3] = {nullptr, nullptr, nullptr};
    int nv = 0;
    for (int i = 0; i < n_in; i++) {
        if ((size_t)in_sizes[i] == MASK_N && mask == nullptr) {
            mask = d_in[i];
        } else if (nv < 3) {
            vkq[nv++] = (const float*)d_in[i];
        }
    }
    const float* value = vkq[0];
    const float* key   = vkq[1];
    const float* query = vkq[2];

    float* out  = (float*)d_out;
    float* attn = out + (size_t)B_ * Q_ * D_;

    static bool attr_done = false;
    if (!attr_done) {
        cudaFuncSetAttribute(k_pv, cudaFuncAttributeMaxDynamicSharedMemorySize, 65536);
        attr_done = true;
    }

    k_probe_mask<<<1, 32>>>((const unsigned int*)mask);

    dim3 g1(S_ / 128, Q_ / 128, B_);
    k_scores<<<g1, 512>>>(query, key, mask, attn);

    dim3 g3(Q_ / 128, B_);
    k_pv<<<g3, 512, 65536>>>(attn, value, out);
}

// round 8
// speedup vs baseline: 1.6701x; 1.6701x over previous
#include <cuda_runtime.h>
#include <cuda_bf16.h>
#include <cstdint>

#define B_ 16
#define Q_ 2048
#define S_ 2048
#define D_ 128
#define NEG_INF __int_as_float(0xff800000)

// byte-level swizzle for 64B rows (R4-verified)
#define SWZ(o) ((o) ^ (((o) >> 3) & 0x70))

__device__ int g_mask_mode;   // 0 = uint8, 1 = int32, 2 = float32

// ---------------------------------------------------------------------------
__global__ void k_probe_mask(const unsigned int* __restrict__ m)
{
    const int lane = threadIdx.x;
    bool i32 = true, f32 = true;
    for (int i = lane; i < 1024; i += 32) {
        unsigned int w = m[i];
        if (w > 1u) i32 = false;
        if (w != 0u && w != 0x3F800000u) f32 = false;
    }
    unsigned bi = __ballot_sync(0xffffffffu, i32);
    unsigned bf = __ballot_sync(0xffffffffu, f32);
    if (lane == 0) g_mask_mode = (bi == 0xffffffffu) ? 1 : ((bf == 0xffffffffu) ? 2 : 0);
}

// ---------------------------------------------------------------------------
__device__ __forceinline__ void split_pack(float x, float y, uint32_t& hi, uint32_t& lo)
{
    __nv_bfloat16 hx = __float2bfloat16_rn(x);
    __nv_bfloat16 hy = __float2bfloat16_rn(y);
    __nv_bfloat16 lx = __float2bfloat16_rn(x - __bfloat162float(hx));
    __nv_bfloat16 ly = __float2bfloat16_rn(y - __bfloat162float(hy));
    hi = (uint32_t)__bfloat16_as_ushort(hx) | ((uint32_t)__bfloat16_as_ushort(hy) << 16);
    lo = (uint32_t)__bfloat16_as_ushort(lx) | ((uint32_t)__bfloat16_as_ushort(ly) << 16);
}

__device__ __forceinline__ void split8(const float4& a, const float4& b, uint4& hi, uint4& lo)
{
    split_pack(a.x, a.y, hi.x, lo.x);
    split_pack(a.z, a.w, hi.y, lo.y);
    split_pack(b.x, b.y, hi.z, lo.z);
    split_pack(b.z, b.w, hi.w, lo.w);
}

__device__ __forceinline__ void mma16816(float (&c)[4], const uint32_t (&a)[4], const uint32_t* b)
{
    asm volatile(
        "mma.sync.aligned.m16n8k16.row.col.f32.bf16.bf16.f32 "
        "{%0,%1,%2,%3}, {%4,%5,%6,%7}, {%8,%9}, {%0,%1,%2,%3};\n"
        : "+f"(c[0]), "+f"(c[1]), "+f"(c[2]), "+f"(c[3])
        : "r"(a[0]), "r"(a[1]), "r"(a[2]), "r"(a[3]), "r"(b[0]), "r"(b[1]));
}

__device__ __forceinline__ void ldsm_x4(uint32_t (&r)[4], uint32_t addr)
{
    asm volatile("ldmatrix.sync.aligned.m8n8.x4.shared.b16 {%0,%1,%2,%3}, [%4];\n"
                 : "=r"(r[0]), "=r"(r[1]), "=r"(r[2]), "=r"(r[3]) : "r"(addr));
}

__device__ __forceinline__ uint32_t sptr(const void* p)
{
    return (uint32_t)__cvta_generic_to_shared(p);
}

// ---------------------------------------------------------------------------
// Kernel 1: scores = mask ? -inf : (Q K^T) * D^-0.5  (3xBF16, ldmatrix feed)
// CTA 128q x 128s, 512 thr (16 warps 4x4, warp tile 32x32), D chunks of 32.
// Double-buffered dynamic smem (2 x 32KB): one sync per chunk; split/STS of
// chunk i+1 overlaps MMAs of chunk i. Epilogue identical to R4 (best-known).
// ---------------------------------------------------------------------------
__global__ __launch_bounds__(512, 1) void k_scores(
    const float* __restrict__ Qm, const float* __restrict__ Km,
    const void* __restrict__ mask, float* __restrict__ P)
{
    extern __shared__ __align__(128) uint8_t sm[];
    // per buffer: Qh:+0  Ql:+8192  Kh:+16384  Kl:+24576 ; buffers at 0 / 32768

    const int b  = blockIdx.z;
    const int q0 = blockIdx.y * 128;
    const int s0 = blockIdx.x * 128;
    const float* Qb = Qm + ((size_t)b * Q_ + q0) * D_;
    const float* Kb = Km + ((size_t)b * S_ + s0) * D_;

    const int tid  = threadIdx.x;
    const int lane = tid & 31;
    const int wid  = tid >> 5;
    const int g    = lane >> 2;
    const int tg   = lane & 3;
    const int mw   = wid >> 2;
    const int nw   = wid & 3;

    float acc[2][4][4];
#pragma unroll
    for (int i = 0; i < 2; i++)
#pragma unroll
        for (int j = 0; j < 4; j++)
#pragma unroll
            for (int k = 0; k < 4; k++) acc[i][j][k] = 0.f;

    // conversion mapping: thread -> row r (0..127), 8-float chunk c (0..3)
    const int r = tid >> 2;
    const int c = tid & 3;
    const uint32_t sts_off = SWZ((uint32_t)(r * 64 + c * 16));

    const uint32_t a_row[2] = { (uint32_t)(mw * 32 + 0  + (lane & 15)),
                                (uint32_t)(mw * 32 + 16 + (lane & 15)) };
    const uint32_t a_chq    = (uint32_t)(lane >> 4);
    const uint32_t b_row[2] = { (uint32_t)(nw * 32 + 0  + (lane & 7) + ((lane & 16) >> 1)),
                                (uint32_t)(nw * 32 + 16 + (lane & 7) + ((lane & 16) >> 1)) };
    const uint32_t b_chq    = (uint32_t)((lane >> 3) & 1);

    // ---- prologue: chunk 0 -> buffer 0 ----
    {
        float4 q0v = *(const float4*)(Qb + (size_t)r * D_ + c * 8);
        float4 q1v = *(const float4*)(Qb + (size_t)r * D_ + c * 8 + 4);
        float4 k0v = *(const float4*)(Kb + (size_t)r * D_ + c * 8);
        float4 k1v = *(const float4*)(Kb + (size_t)r * D_ + c * 8 + 4);
        uint4 h, l;
        split8(q0v, q1v, h, l);
        *(uint4*)(sm + sts_off)        = h;
        *(uint4*)(sm + 8192 + sts_off) = l;
        split8(k0v, k1v, h, l);
        *(uint4*)(sm + 16384 + sts_off) = h;
        *(uint4*)(sm + 24576 + sts_off) = l;
    }
    __syncthreads();

    for (int dc = 0; dc < D_; dc += 32) {
        const uint32_t cur = ((dc >> 5) & 1) * 32768u;
        const uint32_t nxt = cur ^ 32768u;
        const bool more = (dc + 32 < D_);

        float4 q0v, q1v, k0v, k1v;
        if (more) {
            q0v = *(const float4*)(Qb + (size_t)r * D_ + dc + 32 + c * 8);
            q1v = *(const float4*)(Qb + (size_t)r * D_ + dc + 32 + c * 8 + 4);
            k0v = *(const float4*)(Kb + (size_t)r * D_ + dc + 32 + c * 8);
            k1v = *(const float4*)(Kb + (size_t)r * D_ + dc + 32 + c * 8 + 4);
        }

#pragma unroll
        for (int ks = 0; ks < 2; ks++) {
            uint32_t ah[2][4], al[2][4];
#pragma unroll
            for (int mi = 0; mi < 2; mi++) {
                uint32_t off = cur + SWZ(a_row[mi] * 64 + (2 * ks + a_chq) * 16);
                ldsm_x4(ah[mi], sptr(sm) + off);
                ldsm_x4(al[mi], sptr(sm) + 8192 + off);
            }
            uint32_t bh[2][4], bl[2][4];
#pragma unroll
            for (int njp = 0; njp < 2; njp++) {
                uint32_t off = cur + SWZ(b_row[njp] * 64 + (2 * ks + b_chq) * 16);
                ldsm_x4(bh[njp], sptr(sm) + 16384 + off);
                ldsm_x4(bl[njp], sptr(sm) + 24576 + off);
            }
#pragma unroll
            for (int mi = 0; mi < 2; mi++)
#pragma unroll
                for (int njp = 0; njp < 2; njp++)
#pragma unroll
                    for (int j = 0; j < 2; j++) {
                        float (&cacc)[4] = acc[mi][njp * 2 + j];
                        mma16816(cacc, ah[mi], &bh[njp][2 * j]);
                        mma16816(cacc, ah[mi], &bl[njp][2 * j]);
                        mma16816(cacc, al[mi], &bh[njp][2 * j]);
                    }
        }

        if (more) {
            uint4 h, l;
            split8(q0v, q1v, h, l);
            *(uint4*)(sm + nxt + sts_off)        = h;
            *(uint4*)(sm + nxt + 8192 + sts_off) = l;
            split8(k0v, k1v, h, l);
            *(uint4*)(sm + nxt + 16384 + sts_off) = h;
            *(uint4*)(sm + nxt + 24576 + sts_off) = l;
        }
        __syncthreads();
    }

    const float scale = 0.08838834764831845f;  // 128^-0.5
    const int mm = g_mask_mode;
#pragma unroll
    for (int mi = 0; mi < 2; mi++) {
#pragma unroll
        for (int hh = 0; hh < 2; hh++) {
            const int q = q0 + mw * 32 + mi * 16 + hh * 8 + g;
            const size_t rowoff = ((size_t)b * Q_ + q) * (size_t)S_;
#pragma unroll
            for (int nj = 0; nj < 4; nj++) {
                const int s = s0 + nw * 32 + nj * 8 + tg * 2;
                const size_t off = rowoff + s;
                const float v0 = acc[mi][nj][hh * 2 + 0] * scale;
                const float v1 = acc[mi][nj][hh * 2 + 1] * scale;
                bool m0, m1;
                if (mm == 1) {
                    int2 w = *(const int2*)((const int*)mask + off);
                    m0 = w.x != 0; m1 = w.y != 0;
                } else if (mm == 2) {
                    float2 w = *(const float2*)((const float*)mask + off);
                    m0 = w.x != 0.f; m1 = w.y != 0.f;
                } else {
                    const unsigned char* mu = (const unsigned char*)mask + off;
                    m0 = mu[0] != 0; m1 = mu[1] != 0;
                }
                float2 o;
                o.x = m0 ? NEG_INF : v0;
                o.y = m1 ? NEG_INF : v1;
                *(float2*)(P + off) = o;
            }
        }
    }
}

// ---------------------------------------------------------------------------
// Kernel 2: in-place row softmax over S=2048. One block (256 thr) per row.
// ---------------------------------------------------------------------------
__global__ __launch_bounds__(256) void k_softmax(float* __restrict__ P)
{
    __shared__ float red[8];
    const size_t row = blockIdx.x;
    float* p = P + row * (size_t)S_;
    const int tid  = threadIdx.x;
    const int lane = tid & 31;
    const int wid  = tid >> 5;

    float4 v0 = ((const float4*)p)[tid];
    float4 v1 = ((const float4*)p)[tid + 256];

    float m = fmaxf(fmaxf(fmaxf(v0.x, v0.y), fmaxf(v0.z, v0.w)),
                    fmaxf(fmaxf(v1.x, v1.y), fmaxf(v1.z, v1.w)));
#pragma unroll
    for (int o = 16; o; o >>= 1) m = fmaxf(m, __shfl_xor_sync(0xffffffffu, m, o));
    if (lane == 0) red[wid] = m;
    __syncthreads();
    m = red[0];
#pragma unroll
    for (int w = 1; w < 8; w++) m = fmaxf(m, red[w]);
    __syncthreads();

    float e[8];
    e[0] = __expf(v0.x - m); e[1] = __expf(v0.y - m);
    e[2] = __expf(v0.z - m); e[3] = __expf(v0.w - m);
    e[4] = __expf(v1.x - m); e[5] = __expf(v1.y - m);
    e[6] = __expf(v1.z - m); e[7] = __expf(v1.w - m);
    float s = ((e[0] + e[1]) + (e[2] + e[3])) + ((e[4] + e[5]) + (e[6] + e[7]));
#pragma unroll
    for (int o = 16; o; o >>= 1) s += __shfl_xor_sync(0xffffffffu, s, o);
    if (lane == 0) red[wid] = s;
    __syncthreads();
    s = red[0];
#pragma unroll
    for (int w = 1; w < 8; w++) s += red[w];

    const float inv = 1.0f / s;
    v0.x = e[0] * inv; v0.y = e[1] * inv; v0.z = e[2] * inv; v0.w = e[3] * inv;
    v1.x = e[4] * inv; v1.y = e[5] * inv; v1.z = e[6] * inv; v1.w = e[7] * inv;
    ((float4*)p)[tid]       = v0;
    ((float4*)p)[tid + 256] = v1;
}

// ---------------------------------------------------------------------------
// Kernel 3: out = P @ V (3xBF16, ldmatrix feed), P already normalized.
// CTA 128q x 128d, 512 thr, S chunks of 32, double-buffered smem (64KB).
// ---------------------------------------------------------------------------
__global__ __launch_bounds__(512, 1) void k_pv(
    const float* __restrict__ P, const float* __restrict__ V,
    float* __restrict__ O)
{
    extern __shared__ __align__(128) uint8_t sm[];
    // per buffer: Ph:+0  Pl:+8192  Vh:+16384  Vl:+24576 ; buffers at 0 / 32768

    const int b  = blockIdx.y;
    const int q0 = blockIdx.x * 128;
    const float* Pb = P + ((size_t)b * Q_ + q0) * (size_t)S_;
    const float* Vb = V + (size_t)b * S_ * D_;

    const int tid  = threadIdx.x;
    const int lane = tid & 31;
    const int wid  = tid >> 5;
    const int g    = lane >> 2;
    const int tg   = lane & 3;
    const int mw   = wid >> 2;
    const int nw   = wid & 3;

    float acc[2][4][4];
#pragma unroll
    for (int i = 0; i < 2; i++)
#pragma unroll
        for (int j = 0; j < 4; j++)
#pragma unroll
            for (int k = 0; k < 4; k++) acc[i][j][k] = 0.f;

    const int pr = tid >> 2;
    const int pc = tid & 3;
    const uint32_t p_sts = SWZ((uint32_t)(pr * 64 + pc * 16));
    const int vd = tid & 127;
    const int sg = tid >> 7;
    const uint32_t v_sts = SWZ((uint32_t)(vd * 64 + sg * 16));

    const uint32_t a_row[2] = { (uint32_t)(mw * 32 + 0  + (lane & 15)),
                                (uint32_t)(mw * 32 + 16 + (lane & 15)) };
    const uint32_t a_chq    = (uint32_t)(lane >> 4);
    const uint32_t b_row[2] = { (uint32_t)(nw * 32 + 0  + (lane & 7) + ((lane & 16) >> 1)),
                                (uint32_t)(nw * 32 + 16 + (lane & 7) + ((lane & 16) >> 1)) };
    const uint32_t b_chq    = (uint32_t)((lane >> 3) & 1);

    // ---- prologue: chunk 0 -> buffer 0 ----
    {
        float4 pp0 = *(const float4*)(Pb + (size_t)pr * S_ + pc * 8);
        float4 pp1 = *(const float4*)(Pb + (size_t)pr * S_ + pc * 8 + 4);
        uint4 h, l;
        split8(pp0, pp1, h, l);
        *(uint4*)(sm + p_sts)        = h;
        *(uint4*)(sm + 8192 + p_sts) = l;

        float4 va, vbq;
        va.x  = Vb[(size_t)(sg * 8 + 0) * D_ + vd];
        va.y  = Vb[(size_t)(sg * 8 + 1) * D_ + vd];
        va.z  = Vb[(size_t)(sg * 8 + 2) * D_ + vd];
        va.w  = Vb[(size_t)(sg * 8 + 3) * D_ + vd];
        vbq.x = Vb[(size_t)(sg * 8 + 4) * D_ + vd];
        vbq.y = Vb[(size_t)(sg * 8 + 5) * D_ + vd];
        vbq.z = Vb[(size_t)(sg * 8 + 6) * D_ + vd];
        vbq.w = Vb[(size_t)(sg * 8 + 7) * D_ + vd];
        split8(va, vbq, h, l);
        *(uint4*)(sm + 16384 + v_sts) = h;
        *(uint4*)(sm + 24576 + v_sts) = l;
    }
    __syncthreads();

    for (int sc = 0; sc < S_; sc += 32) {
        const uint32_t cur = ((sc >> 5) & 1) * 32768u;
        const uint32_t nxt = cur ^ 32768u;
        const bool more = (sc + 32 < S_);

        float4 pp0, pp1, va, vbq;
        if (more) {
            pp0 = *(const float4*)(Pb + (size_t)pr * S_ + sc + 32 + pc * 8);
            pp1 = *(const float4*)(Pb + (size_t)pr * S_ + sc + 32 + pc * 8 + 4);
            va.x  = Vb[(size_t)(sc + 32 + sg * 8 + 0) * D_ + vd];
            va.y  = Vb[(size_t)(sc + 32 + sg * 8 + 1) * D_ + vd];
            va.z  = Vb[(size_t)(sc + 32 + sg * 8 + 2) * D_ + vd];
            va.w  = Vb[(size_t)(sc + 32 + sg * 8 + 3) * D_ + vd];
            vbq.x = Vb[(size_t)(sc + 32 + sg * 8 + 4) * D_ + vd];
            vbq.y = Vb[(size_t)(sc + 32 + sg * 8 + 5) * D_ + vd];
            vbq.z = Vb[(size_t)(sc + 32 + sg * 8 + 6) * D_ + vd];
            vbq.w = Vb[(size_t)(sc + 32 + sg * 8 + 7) * D_ + vd];
        }

#pragma unroll
        for (int ks = 0; ks < 2; ks++) {
            uint32_t ah[2][4], al[2][4];
#pragma unroll
            for (int mi = 0; mi < 2; mi++) {
                uint32_t off = cur + SWZ(a_row[mi] * 64 + (2 * ks + a_chq) * 16);
                ldsm_x4(ah[mi], sptr(sm) + off);
                ldsm_x4(al[mi], sptr(sm) + 8192 + off);
            }
            uint32_t bh[2][4], bl[2][4];
#pragma unroll
            for (int njp = 0; njp < 2; njp++) {
                uint32_t off = cur + SWZ(b_row[njp] * 64 + (2 * ks + b_chq) * 16);
                ldsm_x4(bh[njp], sptr(sm) + 16384 + off);
                ldsm_x4(bl[njp], sptr(sm) + 24576 + off);
            }
#pragma unroll
            for (int mi = 0; mi < 2; mi++)
#pragma unroll
                for (int njp = 0; njp < 2; njp++)
#pragma unroll
                    for (int j = 0; j < 2; j++) {
                        float (&cacc)[4] = acc[mi][njp * 2 + j];
                        mma16816(cacc, ah[mi], &bh[njp][2 * j]);
                        mma16816(cacc, ah[mi], &bl[njp][2 * j]);
                        mma16816(cacc, al[mi], &bh[njp][2 * j]);
                    }
        }

        if (more) {
            uint4 h, l;
            split8(pp0, pp1, h, l);
            *(uint4*)(sm + nxt + p_sts)        = h;
            *(uint4*)(sm + nxt + 8192 + p_sts) = l;
            split8(va, vbq, h, l);
            *(uint4*)(sm + nxt + 16384 + v_sts) = h;
            *(uint4*)(sm + nxt + 24576 + v_sts) = l;
        }
        __syncthreads();
    }

#pragma unroll
    for (int mi = 0; mi < 2; mi++) {
#pragma unroll
        for (int hh = 0; hh < 2; hh++) {
            const int q = q0 + mw * 32 + mi * 16 + hh * 8 + g;
            float* orow = O + ((size_t)b * Q_ + q) * D_;
#pragma unroll
            for (int nj = 0; nj < 4; nj++) {
                const int d = nw * 32 + nj * 8 + tg * 2;
                float2 o = { acc[mi][nj][hh * 2], acc[mi][nj][hh * 2 + 1] };
                *(float2*)(orow + d) = o;
            }
        }
    }
}

// ---------------------------------------------------------------------------
extern "C" void kernel_launch(void* const* d_in, const int* in_sizes, int n_in,
                              void* d_out, int out_size)
{
    const size_t MASK_N = (size_t)B_ * Q_ * S_;
    const void* mask = nullptr;
    const float* vkq[3] = {nullptr, nullptr, nullptr};
    int nv = 0;
    for (int i = 0; i < n_in; i++) {
        if ((size_t)in_sizes[i] == MASK_N && mask == nullptr) {
            mask = d_in[i];
        } else if (nv < 3) {
            vkq[nv++] = (const float*)d_in[i];
        }
    }
    const float* value = vkq[0];
    const float* key   = vkq[1];
    const float* query = vkq[2];

    float* out  = (float*)d_out;
    float* attn = out + (size_t)B_ * Q_ * D_;

    static bool attr_done = false;
    if (!attr_done) {
        cudaFuncSetAttribute(k_scores, cudaFuncAttributeMaxDynamicSharedMemorySize, 65536);
        cudaFuncSetAttribute(k_pv,     cudaFuncAttributeMaxDynamicSharedMemorySize, 65536);
        attr_done = true;
    }

    k_probe_mask<<<1, 32>>>((const unsigned int*)mask);

    dim3 g1(S_ / 128, Q_ / 128, B_);
    k_scores<<<g1, 512, 65536>>>(query, key, mask, attn);

    k_softmax<<<B_ * Q_, 256>>>(attn);

    dim3 g3(Q_ / 128, B_);
    k_pv<<<g3, 512, 65536>>>(attn, value, out);
}